// round 3
// baseline (speedup 1.0000x reference)
#include <cuda_runtime.h>
#include <math.h>

// Problem shape (fixed by dataset): h (B=4, T=4096, d=512) fp32, raw_alpha (K=4) fp32
// out: (B, T, K, d) fp32
#define T_DIM 4096
#define D_DIM 512
#define K_DIM 4
#define B_MAX 4
#define CHUNK_L 64
#define NCHUNK (T_DIM / CHUNK_L)   // 64

// Scratch (allocation-free: __device__ globals)
__device__ float  g_rtab[T_DIM * K_DIM];                       // r[t][k] = (1-a)/(1-a^{t+1})
__device__ float4 g_alpha4;                                    // alpha per k
__device__ float4 g_powL4;                                     // alpha^CHUNK_L per k
__device__ float  g_E[B_MAX * NCHUNK * D_DIM * K_DIM];         // chunk-end sums -> carries (in place)

__device__ __forceinline__ double sigmoid_clip_d(double x) {
    double a = 1.0 / (1.0 + exp(-x));
    a = fmin(fmax(a, 1e-6), 1.0 - 1e-6);
    return a;
}

// ---------------------------------------------------------------------------
// Kernel A: tables (double precision, one thread per t)
// ---------------------------------------------------------------------------
__global__ void kA_tables(const float* __restrict__ raw_alpha) {
    int t = blockIdx.x * blockDim.x + threadIdx.x;
    if (t >= T_DIM) return;

    double a[K_DIM], la[K_DIM];
#pragma unroll
    for (int k = 0; k < K_DIM; k++) {
        a[k]  = sigmoid_clip_d((double)raw_alpha[k]);
        la[k] = log(a[k]);
    }
#pragma unroll
    for (int k = 0; k < K_DIM; k++) {
        double p = exp(la[k] * (double)(t + 1));   // alpha^{t+1} (underflows to 0 for large t: fine)
        double r = (1.0 - a[k]) / (1.0 - p);
        g_rtab[t * K_DIM + k] = (float)r;
    }
    if (t == 0) {
        g_alpha4 = make_float4((float)a[0], (float)a[1], (float)a[2], (float)a[3]);
        g_powL4  = make_float4((float)exp(la[0] * (double)CHUNK_L),
                               (float)exp(la[1] * (double)CHUNK_L),
                               (float)exp(la[2] * (double)CHUNK_L),
                               (float)exp(la[3] * (double)CHUNK_L));
    }
}

// ---------------------------------------------------------------------------
// Kernel B: per-chunk local scans -> chunk-end sums E[b][c][dd][k]
// Thread handles (b, c, dd4): 4 consecutive d-lanes x 4 k-channels in regs.
// ---------------------------------------------------------------------------
__global__ __launch_bounds__(256) void kB_chunks(const float* __restrict__ h, int Bn) {
    const int DV  = D_DIM / 4;
    int tid = blockIdx.x * blockDim.x + threadIdx.x;
    int ddv = tid % DV;
    int c   = (tid / DV) % NCHUNK;
    int b   = tid / (DV * NCHUNK);
    if (b >= Bn) return;
    int dd = ddv * 4;

    const float4 a4 = g_alpha4;
    float4 S0 = make_float4(0.f, 0.f, 0.f, 0.f);
    float4 S1 = S0, S2 = S0, S3 = S0;

    const float4* hp = (const float4*)(h + ((size_t)b * T_DIM + (size_t)c * CHUNK_L) * D_DIM + dd);

#pragma unroll 8
    for (int j = 0; j < CHUNK_L; j++) {
        float4 h4 = hp[(size_t)j * DV];
        S0.x = fmaf(a4.x, S0.x, h4.x); S0.y = fmaf(a4.y, S0.y, h4.x);
        S0.z = fmaf(a4.z, S0.z, h4.x); S0.w = fmaf(a4.w, S0.w, h4.x);
        S1.x = fmaf(a4.x, S1.x, h4.y); S1.y = fmaf(a4.y, S1.y, h4.y);
        S1.z = fmaf(a4.z, S1.z, h4.y); S1.w = fmaf(a4.w, S1.w, h4.y);
        S2.x = fmaf(a4.x, S2.x, h4.z); S2.y = fmaf(a4.y, S2.y, h4.z);
        S2.z = fmaf(a4.z, S2.z, h4.z); S2.w = fmaf(a4.w, S2.w, h4.z);
        S3.x = fmaf(a4.x, S3.x, h4.w); S3.y = fmaf(a4.y, S3.y, h4.w);
        S3.z = fmaf(a4.z, S3.z, h4.w); S3.w = fmaf(a4.w, S3.w, h4.w);
    }

    float4* Ep = (float4*)&g_E[(((size_t)b * NCHUNK + c) * D_DIM + dd) * K_DIM];
    Ep[0] = S0; Ep[1] = S1; Ep[2] = S2; Ep[3] = S3;
}

// ---------------------------------------------------------------------------
// Kernel C: inter-chunk affine scan, in place: E[b][c][dd][k] becomes the
// carry into chunk c (= global scan value at t = c*L - 1; 0 for c = 0).
// Thread handles (b, dd), all K in a float4. FMA chain is the only serial dep.
// ---------------------------------------------------------------------------
__global__ __launch_bounds__(256) void kC_scan(int Bn) {
    int tid = blockIdx.x * blockDim.x + threadIdx.x;
    int dd  = tid % D_DIM;
    int b   = tid / D_DIM;
    if (b >= Bn) return;

    const float4 pl = g_powL4;
    float4 prev = make_float4(0.f, 0.f, 0.f, 0.f);

    for (int c = 0; c < NCHUNK; c++) {
        float4* p = (float4*)&g_E[(((size_t)b * NCHUNK + c) * D_DIM + dd) * K_DIM];
        float4 e = *p;
        *p = prev;                              // carry into chunk c
        prev.x = fmaf(pl.x, prev.x, e.x);
        prev.y = fmaf(pl.y, prev.y, e.y);
        prev.z = fmaf(pl.z, prev.z, e.z);
        prev.w = fmaf(pl.w, prev.w, e.w);
    }
}

// ---------------------------------------------------------------------------
// Kernel D: final scan + normalize + store.
// S initialized from carry, so the inner loop is exactly the global recurrence.
// ---------------------------------------------------------------------------
__global__ __launch_bounds__(256) void kD_final(const float* __restrict__ h,
                                                float* __restrict__ out, int Bn) {
    const int DV  = D_DIM / 4;
    int tid = blockIdx.x * blockDim.x + threadIdx.x;
    int ddv = tid % DV;
    int c   = (tid / DV) % NCHUNK;
    int b   = tid / (DV * NCHUNK);
    if (b >= Bn) return;
    int dd = ddv * 4;

    const float4 a4 = g_alpha4;

    const float4* Ep = (const float4*)&g_E[(((size_t)b * NCHUNK + c) * D_DIM + dd) * K_DIM];
    float4 S0 = Ep[0], S1 = Ep[1], S2 = Ep[2], S3 = Ep[3];

    const float*  hp = h + ((size_t)b * T_DIM + (size_t)c * CHUNK_L) * D_DIM + dd;
    float*        op = out + ((size_t)b * T_DIM + (size_t)c * CHUNK_L) * K_DIM * D_DIM + dd;
    const float4* rp = (const float4*)&g_rtab[((size_t)c * CHUNK_L) * K_DIM];

#pragma unroll 4
    for (int j = 0; j < CHUNK_L; j++) {
        float4 h4 = *(const float4*)(hp + (size_t)j * D_DIM);
        float4 r4 = rp[j];

        S0.x = fmaf(a4.x, S0.x, h4.x); S0.y = fmaf(a4.y, S0.y, h4.x);
        S0.z = fmaf(a4.z, S0.z, h4.x); S0.w = fmaf(a4.w, S0.w, h4.x);
        S1.x = fmaf(a4.x, S1.x, h4.y); S1.y = fmaf(a4.y, S1.y, h4.y);
        S1.z = fmaf(a4.z, S1.z, h4.y); S1.w = fmaf(a4.w, S1.w, h4.y);
        S2.x = fmaf(a4.x, S2.x, h4.z); S2.y = fmaf(a4.y, S2.y, h4.z);
        S2.z = fmaf(a4.z, S2.z, h4.z); S2.w = fmaf(a4.w, S2.w, h4.z);
        S3.x = fmaf(a4.x, S3.x, h4.w); S3.y = fmaf(a4.y, S3.y, h4.w);
        S3.z = fmaf(a4.z, S3.z, h4.w); S3.w = fmaf(a4.w, S3.w, h4.w);

        // transpose in registers: o_k = {S0[k], S1[k], S2[k], S3[k]} * r[k]
        float4 o0 = make_float4(S0.x * r4.x, S1.x * r4.x, S2.x * r4.x, S3.x * r4.x);
        float4 o1 = make_float4(S0.y * r4.y, S1.y * r4.y, S2.y * r4.y, S3.y * r4.y);
        float4 o2 = make_float4(S0.z * r4.z, S1.z * r4.z, S2.z * r4.z, S3.z * r4.z);
        float4 o3 = make_float4(S0.w * r4.w, S1.w * r4.w, S2.w * r4.w, S3.w * r4.w);

        float* ob = op + (size_t)j * K_DIM * D_DIM;
        *(float4*)(ob + 0 * D_DIM) = o0;
        *(float4*)(ob + 1 * D_DIM) = o1;
        *(float4*)(ob + 2 * D_DIM) = o2;
        *(float4*)(ob + 3 * D_DIM) = o3;
    }
}

// ---------------------------------------------------------------------------
extern "C" void kernel_launch(void* const* d_in, const int* in_sizes, int n_in,
                              void* d_out, int out_size) {
    // Identify inputs by size (robust to ordering): h has B*T*D elems, raw_alpha has K.
    const float* h         = (const float*)d_in[0];
    const float* raw_alpha = (const float*)d_in[1];
    int h_elems = in_sizes[0];
    if (n_in >= 2 && in_sizes[1] > in_sizes[0]) {
        h         = (const float*)d_in[1];
        raw_alpha = (const float*)d_in[0];
        h_elems   = in_sizes[1];
    }
    float* out = (float*)d_out;

    int Bn = h_elems / (T_DIM * D_DIM);
    if (Bn > B_MAX) Bn = B_MAX;
    if (Bn < 1)     Bn = 1;

    // A: tables
    kA_tables<<<(T_DIM + 255) / 256, 256>>>(raw_alpha);

    // B: chunk-local scans
    {
        int total = Bn * NCHUNK * (D_DIM / 4);
        kB_chunks<<<(total + 255) / 256, 256>>>(h, Bn);
    }

    // C: inter-chunk carry scan (in place)
    {
        int total = Bn * D_DIM;
        kC_scan<<<(total + 255) / 256, 256>>>(Bn);
    }

    // D: final scan + normalize
    {
        int total = Bn * NCHUNK * (D_DIM / 4);
        kD_final<<<(total + 255) / 256, 256>>>(h, out, Bn);
    }
}